// round 10
// baseline (speedup 1.0000x reference)
#include <cuda_runtime.h>
#include <math.h>

// Geometry: x (2,1,160,160,16), q/lambda (2,3,160,160,16), f32, C-order.
#define PP 2
#define XD 160
#define YD 160
#define LPB (XD*YD)
#define NV (PP*LPB*4)        // float4 count in x-shaped array = 204800
#define T_ITERS 48
#define TX 16
#define TY 8
#define NBX (XD/TX)          // 10
#define NBY (YD/TY)          // 20
#define NBLK (PP*NBX*NBY)    // 400
#define NTHR (TX*TY*4)       // 512
#define QS 32767.0f
#define FPAD 32              // one 128B line per flag
#define FMAGIC 12582912.0f   // 1.5 * 2^23
#define IMAGIC 0x4B400000

// Only boundary xbar crosses blocks -> double-buffered global (edges only used).
__device__ float4 g_xbg[2][NV];
__device__ unsigned int g_flags[NBLK*FPAD];

__global__ void kreset() {
    int i = blockIdx.x*blockDim.x + threadIdx.x;
    if (i < NBLK) g_flags[i*FPAD] = 0u;
}

__device__ __forceinline__ unsigned int ld_acq(const unsigned int* p) {
    unsigned int v;
    asm volatile("ld.acquire.gpu.global.u32 %0, [%1];" : "=r"(v) : "l"(p) : "memory");
    return v;
}
__device__ __forceinline__ void st_rel(unsigned int* p, unsigned int v) {
    asm volatile("st.release.gpu.global.u32 [%0], %1;" :: "l"(p), "r"(v) : "memory");
}
__device__ __forceinline__ void spin_ge(const unsigned int* p, unsigned int want) {
    while (ld_acq(p) < want) { }
}

__device__ __forceinline__ float shfl_quad(float v, int lane, int delta4) {
    int src = (lane & ~3) | ((lane + delta4) & 3);
    return __shfl_sync(0xffffffffu, v, src);
}
__device__ __forceinline__ int shfl_quad_i(int v, int lane, int delta4) {
    int src = (lane & ~3) | ((lane + delta4) & 3);
    return __shfl_sync(0xffffffffu, v, src);
}
__device__ __forceinline__ float4 f4sub(float4 a, float4 b) {
    return make_float4(a.x-b.x, a.y-b.y, a.z-b.z, a.w-b.w);
}

struct I4 { int a, b, c, d; };
__device__ __forceinline__ I4 unpk(uint2 u) {
    I4 r;
    r.a = ((int)(u.x << 16)) >> 16;
    r.b = ((int)u.x) >> 16;
    r.c = ((int)(u.y << 16)) >> 16;
    r.d = ((int)u.y) >> 16;
    return r;
}
__device__ __forceinline__ uint2 lam2pk(float4 l) {
    int a = __float2int_rn(l.x * QS), b = __float2int_rn(l.y * QS);
    int c = __float2int_rn(l.z * QS), d = __float2int_rn(l.w * QS);
    uint2 u;
    u.x = ((unsigned)a & 0xffffu) | ((unsigned)b << 16);
    u.y = ((unsigned)c & 0xffffu) | ((unsigned)d << 16);
    return u;
}

// Rounded, SATURATED f32 -> s16 via magic number. Clamp to +/-32767 happens in
// the float domain (exact: 12582912+32767 < 2^24), making this bit-equivalent
// to cvt.rni.sat.s16.f32 but entirely on the fma/alu pipes.
__device__ __forceinline__ unsigned rni_sat16(float t) {
    t = fminf(fmaxf(t, -32767.0f), 32767.0f);
    return __float_as_uint(t + FMAGIC);
}
// SIMD packed-s16 dual step: Q' = clamp(sat16(Q + sat16(rni(ss*g))), -L, +L)
__device__ __forceinline__ uint2 qstep_p(uint2 Q, uint2 L, float4 g, float ss) {
    unsigned r0 = rni_sat16(ss * g.x);
    unsigned r1 = rni_sat16(ss * g.y);
    unsigned r2 = rni_sat16(ss * g.z);
    unsigned r3 = rni_sat16(ss * g.w);
    unsigned lo = __byte_perm(r0, r1, 0x5410);   // low s16 of r0 | r1<<16
    unsigned hi = __byte_perm(r2, r3, 0x5410);
    uint2 r;
    r.x = __vmaxs2(__vmins2(__vaddss2(Q.x, lo), L.x), __vsubss2(0u, L.x));
    r.y = __vmaxs2(__vmins2(__vaddss2(Q.y, hi), L.y), __vsubss2(0u, L.y));
    return r;
}
// exact int->float for |i| < 2^22, no convert pipe
__device__ __forceinline__ float i2f_small(int i) {
    return __int_as_float(IMAGIC + i) - FMAGIC;
}

__global__ void __launch_bounds__(NTHR, 3) kpersist(
    const float4* __restrict__ xn, const float4* __restrict__ lam,
    float4* __restrict__ out,
    float sigma, float sigma_s, float inv1ps, float tau, float tau_s, float theta)
{
    __shared__ float4 sxb[TX][TY][4];        // xbar tile (current gen)
    __shared__ float4 sxn[NTHR];             // noisy input (constant)
    __shared__ uint2  slam[3*NTHR];          // lambda int16 packed (constant)
    __shared__ uint2  sq0[TX+1][TY][4];      // Q0' with left halo at [0]
    __shared__ uint2  sq1h[TX][4];           // Q1 halo col (y-dir uses shfl)

    int bid = blockIdx.x;
    int pp  = bid / (NBX*NBY);
    int t   = bid % (NBX*NBY);
    int bx  = t / NBY, by = t % NBY;
    int x0g = bx*TX, y0g = by*TY;

    int tid  = threadIdx.x;
    int quad = tid & 3;
    int ll   = tid >> 2;           // 0..127
    int lx   = ll >> 3;            // 0..15  (== warp index)
    int ly   = ll & 7;             // 0..7
    int lane = tid & 31;

    int base   = pp * LPB;
    int gx = x0g + lx, gy = y0g + ly;
    int line2d = gx*YD + gy;
    int gid    = (base + line2d)*4 + quad;

    // Out-of-tile +1 neighbor global indices (edge threads only).
    int xti = (base + ((x0g+TX) % XD)*YD + gy)*4 + quad;
    int yti = (base + gx*YD + ((y0g+TY) % YD))*4 + quad;

    // Lattice neighbors (flag sources).
    int bxm = (bx == 0) ? NBX-1 : bx-1;
    int bxp = (bx == NBX-1) ? 0 : bx+1;
    int bym = (by == 0) ? NBY-1 : by-1;
    int byp = (by == NBY-1) ? 0 : by+1;
    const unsigned int* fxm = &g_flags[((pp*NBX + bxm)*NBY + by )*FPAD]; // -x (halo q0)
    const unsigned int* fxp = &g_flags[((pp*NBX + bxp)*NBY + by )*FPAD]; // +x (edge)
    const unsigned int* fym = &g_flags[((pp*NBX + bx )*NBY + bym)*FPAD]; // -y (halo q1)
    const unsigned int* fyp = &g_flags[((pp*NBX + bx )*NBY + byp)*FPAD]; // +y (edge)
    unsigned int* myflag = &g_flags[bid*FPAD];

    bool pub = (lx == 0) | (lx == TX-1) | (ly == 0) | (ly == TY-1);
    bool xedge = (lx == TX-1);
    bool yedge = (ly == TY-1);

    // ---- prologue ----
    float4 v   = xn[gid];
    float4 pv  = v, x0v = v, xbv = v;
    sxn[tid] = v;
    #pragma unroll
    for (int d = 0; d < 3; d++)
        slam[d*NTHR + tid] = lam2pk(lam[((pp*3+d)*LPB + line2d)*4 + quad]);

    uint2 Q0 = make_uint2(0u,0u), Q1 = make_uint2(0u,0u), Q2 = make_uint2(0u,0u);

    sxb[lx][ly][quad] = v;
    if (pub) g_xbg[0][gid] = v;

    // ---- halo-tracker roles (threads 0..95; warp 0 -> nb(-x), warps 1,2 -> nb(-y)) ----
    int    hgid = 0;
    uint2  hQ = make_uint2(0u,0u), hL = make_uint2(0u,0u);
    float4* hsrc = 0;
    uint2*  hdst = 0;
    if (tid < 32) {                      // Q0 halo line (x0g-1, y0g+h)
        int h   = tid >> 2;
        int hx  = (x0g == 0) ? XD-1 : x0g-1;
        int h2d = hx*YD + (y0g + h);
        hgid = (base + h2d)*4 + quad;
        hL   = lam2pk(lam[((pp*3+0)*LPB + h2d)*4 + quad]);
        hsrc = &sxb[0][h][quad];
        hdst = &sq0[0][h][quad];
    } else if (tid < 96) {               // Q1 halo line (x0g+h, y0g-1)
        int h   = (tid - 32) >> 2;
        int hy  = (y0g == 0) ? YD-1 : y0g-1;
        int h2d = (x0g + h)*YD + hy;
        hgid = (base + h2d)*4 + quad;
        hL   = lam2pk(lam[((pp*3+1)*LPB + h2d)*4 + quad]);
        hsrc = &sxb[h][0][quad];
        hdst = &sq1h[h][quad];
    }

    __syncthreads();
    if (tid == 0) st_rel(myflag, 1u);    // xbar gen 0 published

    for (int k = 0; k < T_ITERS; k++) {
        const float4* gin = g_xbg[k & 1];
        unsigned int want = (unsigned int)(k + 1);

        // ===== Phase A: local-only work (overlaps neighbor flag latency) =====
        float nxt = shfl_quad(xbv.x, lane, 1);
        float4 gtv = make_float4(xbv.y-xbv.x, xbv.z-xbv.y, xbv.w-xbv.z, nxt-xbv.w);
        uint2 L2p = slam[2*NTHR+tid];
        Q2 = qstep_p(Q2, L2p, gtv, sigma_s);
        int q2d   = ((int)Q2.y) >> 16;
        int prevw = shfl_quad_i(q2d, lane, -1);

        float4 xnv = sxn[tid];
        pv.x = (pv.x + sigma*(xbv.x - xnv.x)) * inv1ps;
        pv.y = (pv.y + sigma*(xbv.y - xnv.y)) * inv1ps;
        pv.z = (pv.z + sigma*(xbv.z - xnv.z)) * inv1ps;
        pv.w = (pv.w + sigma*(xbv.w - xnv.w)) * inv1ps;

        float4 xbx, xby;
        if (!xedge) xbx = sxb[lx+1][ly][quad];
        if (!yedge) xby = sxb[lx][ly+1][quad];

        // ===== Phase B: flag-gated global reads =====
        if (xedge) { spin_ge(fxp, want); xbx = __ldcv(gin + xti); }   // whole warp 15
        if (yedge) { spin_ge(fyp, want); xby = __ldcv(gin + yti); }   // 4 lanes/warp

        float4 gxv = f4sub(xbx, xbv);
        float4 gyv = f4sub(xby, xbv);

        uint2 L0p = slam[tid], L1p = slam[NTHR+tid];
        Q0 = qstep_p(Q0, L0p, gxv, sigma_s); sq0[lx+1][ly][quad] = Q0;
        Q1 = qstep_p(Q1, L1p, gyv, sigma_s);

        uint2 Q1u;
        Q1u.x = __shfl_up_sync(0xffffffffu, Q1.x, 4);
        Q1u.y = __shfl_up_sync(0xffffffffu, Q1.y, 4);

        // halo Q tracked locally (bitwise = neighbor's owner value)
        if (tid < 32) {
            spin_ge(fxm, want);
            float4 a = __ldcv(gin + hgid);
            float4 b = *hsrc;
            hQ = qstep_p(hQ, hL, f4sub(b, a), sigma_s);
            *hdst = hQ;
        } else if (tid < 96) {
            spin_ge(fym, want);
            float4 a = __ldcv(gin + hgid);
            float4 b = *hsrc;
            hQ = qstep_p(hQ, hL, f4sub(b, a), sigma_s);
            *hdst = hQ;
        }

        __syncthreads();   // sq0/sq1h ready; all 4 flags observed >= want

        uint2 q0mp = sq0[lx][ly][quad];
        uint2 q1mp = (ly == 0) ? sq1h[lx][quad] : Q1u;

        I4 q0  = unpk(Q0),   q1  = unpk(Q1),   q2 = unpk(Q2);
        I4 q0m = unpk(q0mp), q1m = unpk(q1mp);

        int adja = (q0m.a - q0.a) + (q1m.a - q1.a) + (prevw - q2.a);
        int adjb = (q0m.b - q0.b) + (q1m.b - q1.b) + (q2.a  - q2.b);
        int adjc = (q0m.c - q0.c) + (q1m.c - q1.c) + (q2.b  - q2.c);
        int adjd = (q0m.d - q0.d) + (q1m.d - q1.d) + (q2.c  - q2.d);

        float4 x1;
        x1.x = x0v.x - tau*pv.x - tau_s*i2f_small(adja);
        x1.y = x0v.y - tau*pv.y - tau_s*i2f_small(adjb);
        x1.z = x0v.z - tau*pv.z - tau_s*i2f_small(adjc);
        x1.w = x0v.w - tau*pv.w - tau_s*i2f_small(adjd);

        float opt = 1.0f + theta;
        float4 xbn;
        xbn.x = opt*x1.x - theta*x0v.x;
        xbn.y = opt*x1.y - theta*x0v.y;
        xbn.z = opt*x1.z - theta*x0v.z;
        xbn.w = opt*x1.w - theta*x0v.w;

        x0v = x1;
        xbv = xbn;

        if (k < T_ITERS-1) {
            if (pub) g_xbg[(k+1) & 1][gid] = xbv;   // boundary only
            sxb[lx][ly][quad] = xbv;
            __syncthreads();
            if (tid == 0) st_rel(myflag, (unsigned int)(k + 2));
        }
    }

    out[gid] = x0v;                        // x1 after 48 iterations
}

extern "C" void kernel_launch(void* const* d_in, const int* in_sizes, int n_in,
                              void* d_out, int out_size) {
    const float4* x   = (const float4*)d_in[0];
    const float4* lam = (const float4*)d_in[1];
    float4* out = (float4*)d_out;

    cudaFuncSetAttribute(kpersist, cudaFuncAttributePreferredSharedMemoryCarveout, 100);

    float L     = sqrtf(13.0f);
    float s10   = 1.0f / (1.0f + expf(-10.0f));
    float sigma = s10 / L;
    float tau   = s10 / L;
    float theta = s10;
    float inv1ps  = 1.0f / (1.0f + sigma);
    float sigma_s = sigma * QS;
    float tau_s   = tau / QS;

    kreset<<<1, NBLK>>>();
    kpersist<<<NBLK, NTHR>>>(x, lam, out, sigma, sigma_s, inv1ps, tau, tau_s, theta);
}

// round 11
// speedup vs baseline: 1.0327x; 1.0327x over previous
#include <cuda_runtime.h>
#include <math.h>

// Geometry: x (2,1,160,160,16), q/lambda (2,3,160,160,16), f32, C-order.
#define PP 2
#define XD 160
#define YD 160
#define LPB (XD*YD)
#define NV (PP*LPB*4)        // float4 count in x-shaped array = 204800
#define T_ITERS 48
#define TX 16
#define TY 8
#define NBX (XD/TX)          // 10
#define NBY (YD/TY)          // 20
#define NBLK (PP*NBX*NBY)    // 400
#define NTHR (TX*TY*4)       // 512
#define QS 32767.0f
#define FPAD 32              // one 128B line per flag
#define FMAGIC 12582912.0f   // 1.5 * 2^23
#define IMAGIC 0x4B400000

// Only boundary xbar crosses blocks -> double-buffered global (edges only used).
__device__ float4 g_xbg[2][NV];
__device__ unsigned int g_flags[NBLK*FPAD];

__global__ void kreset() {
    int i = blockIdx.x*blockDim.x + threadIdx.x;
    if (i < NBLK) g_flags[i*FPAD] = 0u;
}

__device__ __forceinline__ unsigned int ld_acq(const unsigned int* p) {
    unsigned int v;
    asm volatile("ld.acquire.gpu.global.u32 %0, [%1];" : "=r"(v) : "l"(p) : "memory");
    return v;
}
__device__ __forceinline__ void st_rel(unsigned int* p, unsigned int v) {
    asm volatile("st.release.gpu.global.u32 [%0], %1;" :: "l"(p), "r"(v) : "memory");
}

__device__ __forceinline__ float shfl_quad(float v, int lane, int delta4) {
    int src = (lane & ~3) | ((lane + delta4) & 3);
    return __shfl_sync(0xffffffffu, v, src);
}
__device__ __forceinline__ int shfl_quad_i(int v, int lane, int delta4) {
    int src = (lane & ~3) | ((lane + delta4) & 3);
    return __shfl_sync(0xffffffffu, v, src);
}
__device__ __forceinline__ float4 f4sub(float4 a, float4 b) {
    return make_float4(a.x-b.x, a.y-b.y, a.z-b.z, a.w-b.w);
}

struct I4 { int a, b, c, d; };
__device__ __forceinline__ I4 unpk(uint2 u) {
    I4 r;
    r.a = ((int)(u.x << 16)) >> 16;
    r.b = ((int)u.x) >> 16;
    r.c = ((int)(u.y << 16)) >> 16;
    r.d = ((int)u.y) >> 16;
    return r;
}
__device__ __forceinline__ uint2 lam2pk(float4 l) {
    int a = __float2int_rn(l.x * QS), b = __float2int_rn(l.y * QS);
    int c = __float2int_rn(l.z * QS), d = __float2int_rn(l.w * QS);
    uint2 u;
    u.x = ((unsigned)a & 0xffffu) | ((unsigned)b << 16);
    u.y = ((unsigned)c & 0xffffu) | ((unsigned)d << 16);
    return u;
}

// Rounded, SATURATED f32 -> s16 via magic number. Clamp to +/-32767 in the
// float domain (exact: 12582912+32767 < 2^24): bit-equivalent to
// cvt.rni.sat.s16.f32, but entirely on fma/alu pipes (no XU converts).
__device__ __forceinline__ unsigned rni_sat16(float t) {
    t = fminf(fmaxf(t, -32767.0f), 32767.0f);
    return __float_as_uint(t + FMAGIC);
}
// SIMD packed-s16 dual step: Q' = clamp(sat16(Q + rni_sat(ss*g)), -L, +L)
__device__ __forceinline__ uint2 qstep_p(uint2 Q, uint2 L, float4 g, float ss) {
    unsigned r0 = rni_sat16(ss * g.x);
    unsigned r1 = rni_sat16(ss * g.y);
    unsigned r2 = rni_sat16(ss * g.z);
    unsigned r3 = rni_sat16(ss * g.w);
    unsigned lo = __byte_perm(r0, r1, 0x5410);
    unsigned hi = __byte_perm(r2, r3, 0x5410);
    uint2 r;
    r.x = __vmaxs2(__vmins2(__vaddss2(Q.x, lo), L.x), __vsubss2(0u, L.x));
    r.y = __vmaxs2(__vmins2(__vaddss2(Q.y, hi), L.y), __vsubss2(0u, L.y));
    return r;
}
// exact int->float for |i| < 2^22, no convert pipe
__device__ __forceinline__ float i2f_small(int i) {
    return __int_as_float(IMAGIC + i) - FMAGIC;
}

__global__ void __launch_bounds__(NTHR, 3) kpersist(
    const float4* __restrict__ xn, const float4* __restrict__ lam,
    float4* __restrict__ out,
    float sigma, float sigma_s, float inv1ps, float tau, float tau_s, float theta)
{
    __shared__ float4 sxb[TX][TY][4];        // xbar tile (current gen)
    __shared__ float4 sxn[NTHR];             // noisy input (constant)
    __shared__ uint2  slam[3*NTHR];          // lambda int16 packed (constant)
    __shared__ uint2  sq0[TX+1][TY][4];      // Q0' with left halo at [0]
    __shared__ uint2  sq1h[TX][4];           // Q1 halo col (y-dir uses shfl)

    int bid = blockIdx.x;
    int pp  = bid / (NBX*NBY);
    int t   = bid % (NBX*NBY);
    int bx  = t / NBY, by = t % NBY;
    int x0g = bx*TX, y0g = by*TY;

    int tid  = threadIdx.x;
    int quad = tid & 3;
    int ll   = tid >> 2;           // 0..127
    int lx   = ll >> 3;            // 0..15  (== warp index)
    int ly   = ll & 7;             // 0..7
    int lane = tid & 31;

    int base   = pp * LPB;
    int gx = x0g + lx, gy = y0g + ly;
    int line2d = gx*YD + gy;
    int gid    = (base + line2d)*4 + quad;

    // Out-of-tile +1 neighbor global indices (edge threads only).
    int xti = (base + ((x0g+TX) % XD)*YD + gy)*4 + quad;
    int yti = (base + gx*YD + ((y0g+TY) % YD))*4 + quad;

    // Lattice neighbors (flag sources). Centralized wait: threads 0..3 spin.
    int bxm = (bx == 0) ? NBX-1 : bx-1;
    int bxp = (bx == NBX-1) ? 0 : bx+1;
    int bym = (by == 0) ? NBY-1 : by-1;
    int byp = (by == NBY-1) ? 0 : by+1;
    const unsigned int* nflag = 0;
    if      (tid == 0) nflag = &g_flags[((pp*NBX + bxm)*NBY + by )*FPAD];
    else if (tid == 1) nflag = &g_flags[((pp*NBX + bxp)*NBY + by )*FPAD];
    else if (tid == 2) nflag = &g_flags[((pp*NBX + bx )*NBY + bym)*FPAD];
    else if (tid == 3) nflag = &g_flags[((pp*NBX + bx )*NBY + byp)*FPAD];
    unsigned int* myflag = &g_flags[bid*FPAD];

    bool pub = (lx == 0) | (lx == TX-1) | (ly == 0) | (ly == TY-1);
    bool xedge = (lx == TX-1);
    bool yedge = (ly == TY-1);

    // ---- prologue ----
    float4 v   = xn[gid];
    float4 pv  = v, x0v = v, xbv = v;
    sxn[tid] = v;
    #pragma unroll
    for (int d = 0; d < 3; d++)
        slam[d*NTHR + tid] = lam2pk(lam[((pp*3+d)*LPB + line2d)*4 + quad]);

    uint2 Q0 = make_uint2(0u,0u), Q1 = make_uint2(0u,0u), Q2 = make_uint2(0u,0u);

    sxb[lx][ly][quad] = v;
    if (pub) g_xbg[0][gid] = v;

    // ---- halo-tracker roles (threads 0..95) ----
    int    hgid = 0;
    uint2  hQ = make_uint2(0u,0u), hL = make_uint2(0u,0u);
    float4* hsrc = 0;
    uint2*  hdst = 0;
    if (tid < 32) {                      // Q0 halo line (x0g-1, y0g+h)
        int h   = tid >> 2;
        int hx  = (x0g == 0) ? XD-1 : x0g-1;
        int h2d = hx*YD + (y0g + h);
        hgid = (base + h2d)*4 + quad;
        hL   = lam2pk(lam[((pp*3+0)*LPB + h2d)*4 + quad]);
        hsrc = &sxb[0][h][quad];
        hdst = &sq0[0][h][quad];
    } else if (tid < 96) {               // Q1 halo line (x0g+h, y0g-1)
        int h   = (tid - 32) >> 2;
        int hy  = (y0g == 0) ? YD-1 : y0g-1;
        int h2d = (x0g + h)*YD + hy;
        hgid = (base + h2d)*4 + quad;
        hL   = lam2pk(lam[((pp*3+1)*LPB + h2d)*4 + quad]);
        hsrc = &sxb[h][0][quad];
        hdst = &sq1h[h][quad];
    }

    __syncthreads();
    if (tid == 0) st_rel(myflag, 1u);    // xbar gen 0 published

    for (int k = 0; k < T_ITERS; k++) {
        const float4* gin = g_xbg[k & 1];
        unsigned int want = (unsigned int)(k + 1);

        // ===== Phase A: local-only work, overlaps the flag wait below =====
        float nxt = shfl_quad(xbv.x, lane, 1);
        float4 gtv = make_float4(xbv.y-xbv.x, xbv.z-xbv.y, xbv.w-xbv.z, nxt-xbv.w);
        uint2 L2p = slam[2*NTHR+tid];
        Q2 = qstep_p(Q2, L2p, gtv, sigma_s);
        int q2d   = ((int)Q2.y) >> 16;
        int prevw = shfl_quad_i(q2d, lane, -1);

        float4 xnv = sxn[tid];
        pv.x = (pv.x + sigma*(xbv.x - xnv.x)) * inv1ps;
        pv.y = (pv.y + sigma*(xbv.y - xnv.y)) * inv1ps;
        pv.z = (pv.z + sigma*(xbv.z - xnv.z)) * inv1ps;
        pv.w = (pv.w + sigma*(xbv.w - xnv.w)) * inv1ps;

        float4 xbx, xby;
        if (!xedge) xbx = sxb[lx+1][ly][quad];
        if (!yedge) xby = sxb[lx][ly+1][quad];

        // ===== Centralized wait: 4 threads spin, the rest sleep on BAR =====
        if (nflag) { while (ld_acq(nflag) < want) { } }
        __syncthreads();

        // ===== Phase B: cross-block reads + dual updates =====
        if (xedge) xbx = __ldcv(gin + xti);
        if (yedge) xby = __ldcv(gin + yti);

        float4 gxv = f4sub(xbx, xbv);
        float4 gyv = f4sub(xby, xbv);

        uint2 L0p = slam[tid], L1p = slam[NTHR+tid];
        Q0 = qstep_p(Q0, L0p, gxv, sigma_s); sq0[lx+1][ly][quad] = Q0;
        Q1 = qstep_p(Q1, L1p, gyv, sigma_s);

        uint2 Q1u;
        Q1u.x = __shfl_up_sync(0xffffffffu, Q1.x, 4);
        Q1u.y = __shfl_up_sync(0xffffffffu, Q1.y, 4);

        // halo Q tracked locally (bitwise = neighbor's owner value)
        if (tid < 96) {
            float4 a = __ldcv(gin + hgid);
            float4 b = *hsrc;
            hQ = qstep_p(hQ, hL, f4sub(b, a), sigma_s);
            *hdst = hQ;
        }

        __syncthreads();   // sq0/sq1h ready

        uint2 q0mp = sq0[lx][ly][quad];
        uint2 q1mp = (ly == 0) ? sq1h[lx][quad] : Q1u;

        I4 q0  = unpk(Q0),   q1  = unpk(Q1),   q2 = unpk(Q2);
        I4 q0m = unpk(q0mp), q1m = unpk(q1mp);

        int adja = (q0m.a - q0.a) + (q1m.a - q1.a) + (prevw - q2.a);
        int adjb = (q0m.b - q0.b) + (q1m.b - q1.b) + (q2.a  - q2.b);
        int adjc = (q0m.c - q0.c) + (q1m.c - q1.c) + (q2.b  - q2.c);
        int adjd = (q0m.d - q0.d) + (q1m.d - q1.d) + (q2.c  - q2.d);

        float4 x1;
        x1.x = x0v.x - tau*pv.x - tau_s*i2f_small(adja);
        x1.y = x0v.y - tau*pv.y - tau_s*i2f_small(adjb);
        x1.z = x0v.z - tau*pv.z - tau_s*i2f_small(adjc);
        x1.w = x0v.w - tau*pv.w - tau_s*i2f_small(adjd);

        float opt = 1.0f + theta;
        float4 xbn;
        xbn.x = opt*x1.x - theta*x0v.x;
        xbn.y = opt*x1.y - theta*x0v.y;
        xbn.z = opt*x1.z - theta*x0v.z;
        xbn.w = opt*x1.w - theta*x0v.w;

        x0v = x1;
        xbv = xbn;

        if (k < T_ITERS-1) {
            if (pub) g_xbg[(k+1) & 1][gid] = xbv;   // boundary only
            sxb[lx][ly][quad] = xbv;
            __syncthreads();
            if (tid == 0) st_rel(myflag, (unsigned int)(k + 2));
        }
    }

    out[gid] = x0v;                        // x1 after 48 iterations
}

extern "C" void kernel_launch(void* const* d_in, const int* in_sizes, int n_in,
                              void* d_out, int out_size) {
    const float4* x   = (const float4*)d_in[0];
    const float4* lam = (const float4*)d_in[1];
    float4* out = (float4*)d_out;

    cudaFuncSetAttribute(kpersist, cudaFuncAttributePreferredSharedMemoryCarveout, 100);

    float L     = sqrtf(13.0f);
    float s10   = 1.0f / (1.0f + expf(-10.0f));
    float sigma = s10 / L;
    float tau   = s10 / L;
    float theta = s10;
    float inv1ps  = 1.0f / (1.0f + sigma);
    float sigma_s = sigma * QS;
    float tau_s   = tau / QS;

    kreset<<<1, NBLK>>>();
    kpersist<<<NBLK, NTHR>>>(x, lam, out, sigma, sigma_s, inv1ps, tau, tau_s, theta);
}